// round 12
// baseline (speedup 1.0000x reference)
#include <cuda_runtime.h>

// PS-ROI-Align, fixed dims:
//   input: (N=4, C=490, H=100, W=100) f32
//   rois:  (K=2048, 5) f32  [batch, x1, y1, x2, y2]
//   out:   (K, 10, 7, 7) f32,  POOL=7, SCALE=1/16, GRID=2
//
// Persistent double-buffered smem pipeline:
//   prep: bucket rois by batch, precompute per-roi (x1, y1, bsw, bsh).
//   main: 296 persistent CTAs (2/SM), each walks planes p, p+296, ...
//         Dynamic smem holds two 40KB plane buffers; cp.async prefetches
//         plane i+1 while computing plane i -> DRAM streams continuously.

#define C_TOT   490
#define HH      100
#define WW      100
#define POOL    7
#define SSCALE  0.0625f
#define PLANE   (HH * WW)
#define PLANE_PAD (PLANE + 16)
#define K_ROIS  2048
#define NBATCH  4
#define NPLANES (C_TOT * NBATCH)
#define NCTAS   296
#define SMEM_BYTES (2 * PLANE_PAD * 4)

__device__ int    g_count[NBATCH];
__device__ int    g_list[NBATCH][K_ROIS];
__device__ float4 g_par [NBATCH][K_ROIS];   // x1, y1, bsw, bsh

__global__ void prep_kernel(const float* __restrict__ rois)
{
    int t = threadIdx.x;
    if (t < NBATCH) g_count[t] = 0;
    __syncthreads();
    for (int k = t; k < K_ROIS; k += blockDim.x) {
        const float* roi = rois + k * 5;
        int   b  = (int)roi[0];
        float x1 = roi[1] * SSCALE - 0.5f;
        float y1 = roi[2] * SSCALE - 0.5f;
        float x2 = roi[3] * SSCALE - 0.5f;
        float y2 = roi[4] * SSCALE - 0.5f;
        int i = atomicAdd(&g_count[b], 1);
        g_list[b][i] = k;
        g_par[b][i]  = make_float4(x1, y1,
                                   (x2 - x1) * (1.0f / POOL),
                                   (y2 - y1) * (1.0f / POOL));
    }
}

__device__ __forceinline__ void issue_plane_load(
    float* dst, const float* __restrict__ input, int p, int t)
{
    // plane p: b = p / C_TOT, r = p % C_TOT; contiguous 40KB from input
    const float4* src = (const float4*)(input + (long)p * PLANE);
    float4* d4 = (float4*)dst;
    #pragma unroll
    for (int i = 0; i < 10; ++i) {
        int j = t + i * 256;
        if (j < PLANE / 4) {
            unsigned saddr = (unsigned)__cvta_generic_to_shared(d4 + j);
            asm volatile("cp.async.cg.shared.global [%0], [%1], 16;\n"
                         :: "r"(saddr), "l"(src + j) : "memory");
        }
    }
    asm volatile("cp.async.commit_group;\n" ::: "memory");
}

__device__ __forceinline__ void compute_plane(
    const float* __restrict__ s_plane, int p, int t,
    float* __restrict__ out)
{
    int b = p / C_TOT;
    int r = p - b * C_TOT;
    int pw = r % POOL;
    int ph = (r / POOL) % POOL;
    float cpw0 = (float)pw + 0.25f, cpw1 = (float)pw + 0.75f;
    float cph0 = (float)ph + 0.25f, cph1 = (float)ph + 0.75f;

    int n = g_count[b];
    for (int i = t; i < n; i += 256) {
        int    k = g_list[b][i];
        float4 P = g_par[b][i];
        float x1 = P.x, y1 = P.y, bsw = P.z, bsh = P.w;

        // ---- x taps ----
        float tx0 = fmaxf(x1 + cpw0 * bsw, 0.0f);
        float tx1 = fmaxf(x1 + cpw1 * bsw, 0.0f);
        int xl0 = min((int)tx0, WW - 1);
        int xl1 = min((int)tx1, WW - 1);
        int xh0 = min(xl0 + 1, WW - 1);
        int xh1 = min(xl1 + 1, WW - 1);
        float fx0 = (xl0 >= WW - 1) ? 0.0f : tx0 - (float)xl0;
        float fx1 = (xl1 >= WW - 1) ? 0.0f : tx1 - (float)xl1;

        // ---- y taps ----
        float ty0 = fmaxf(y1 + cph0 * bsh, 0.0f);
        float ty1 = fmaxf(y1 + cph1 * bsh, 0.0f);
        int yl0 = min((int)ty0, HH - 1);
        int yl1 = min((int)ty1, HH - 1);
        int yh0 = min(yl0 + 1, HH - 1);
        int yh1 = min(yl1 + 1, HH - 1);
        float fy0 = (yl0 >= HH - 1) ? 0.0f : ty0 - (float)yl0;
        float fy1 = (yl1 >= HH - 1) ? 0.0f : ty1 - (float)yl1;

        float a0 = 1.0f - fy0, a1 = fy0;
        float a2 = 1.0f - fy1, a3 = fy1;

        // ---- branch-free row dedup ----
        bool same_pair = (yl1 == yl0);
        bool shift_one = (yl1 == yh0);
        bool act2 = !same_pair;
        bool act3 = !same_pair && !shift_one;
        int  row2 = shift_one ? yh1 : yl1;
        float wr0 = a0 + (same_pair ? a2 : 0.0f);
        float wr1 = a1 + (same_pair ? a3 : (shift_one ? a2 : 0.0f));
        float wr2 = shift_one ? a3 : a2;
        float wr3 = a3;

        // ---- aligned x window ----
        int wbase = xl0 & ~3;
        int o_l0 = xl0 - wbase, o_h0 = xh0 - wbase;
        int o_l1 = xl1 - wbase, o_h1 = xh1 - wbase;
        bool needB = (o_h1 > 3);
        bool needC = (o_h1 > 7);        // == 8

        const float* rowbase = s_plane + wbase;
        const float4* p0 = (const float4*)(rowbase + yl0 * WW);
        const float4* p1 = (const float4*)(rowbase + yh0 * WW);
        const float4* p2 = (const float4*)(rowbase + row2 * WW);
        const float4* p3 = (const float4*)(rowbase + yh1 * WW);

        // ---- predicated smem loads ----
        float4 Z  = make_float4(0.f, 0.f, 0.f, 0.f);
        float4 A0, A1, A2 = Z, A3 = Z, B0 = Z, B1 = Z, B2 = Z, B3 = Z;
        float  c0 = 0.f, c1 = 0.f, c2 = 0.f, c3 = 0.f;
        A0 = *p0;
        A1 = *p1;
        if (act2)          A2 = *p2;
        if (act3)          A3 = *p3;
        if (needB)         B0 = p0[1];
        if (needB)         B1 = p1[1];
        if (needB && act2) B2 = p2[1];
        if (needB && act3) B3 = p3[1];
        if (needC)         c0 = ((const float*)p0)[8];
        if (needC)         c1 = ((const float*)p1)[8];
        if (needC && act2) c2 = ((const float*)p2)[8];
        if (needC && act3) c3 = ((const float*)p3)[8];

        // x-weight vector over window floats 0..7 (tap 8 via C scalars)
        float w[8];
        #pragma unroll
        for (int j = 0; j < 8; ++j) {
            float v = (j == o_l0) ? (1.0f - fx0) : 0.0f;
            v += (j == o_h0) ? fx0 : 0.0f;
            v += (j == o_l1) ? (1.0f - fx1) : 0.0f;
            v += (j == o_h1) ? fx1 : 0.0f;
            w[j] = v;
        }

        float ax = wr0 * A0.x + wr1 * A1.x + wr2 * A2.x + wr3 * A3.x;
        float ay = wr0 * A0.y + wr1 * A1.y + wr2 * A2.y + wr3 * A3.y;
        float az = wr0 * A0.z + wr1 * A1.z + wr2 * A2.z + wr3 * A3.z;
        float aw = wr0 * A0.w + wr1 * A1.w + wr2 * A2.w + wr3 * A3.w;
        float bx = wr0 * B0.x + wr1 * B1.x + wr2 * B2.x + wr3 * B3.x;
        float by = wr0 * B0.y + wr1 * B1.y + wr2 * B2.y + wr3 * B3.y;
        float bz = wr0 * B0.z + wr1 * B1.z + wr2 * B2.z + wr3 * B3.z;
        float bw = wr0 * B0.w + wr1 * B1.w + wr2 * B2.w + wr3 * B3.w;
        float cc = wr0 * c0   + wr1 * c1   + wr2 * c2   + wr3 * c3;

        float acc = ax * w[0] + ay * w[1] + az * w[2] + aw * w[3]
                  + bx * w[4] + by * w[5] + bz * w[6] + bw * w[7]
                  + (needC ? cc * fx1 : 0.0f);

        out[k * C_TOT + r] = acc * 0.25f;
    }
}

__global__ __launch_bounds__(256) void psroi_main(
    const float* __restrict__ input,
    float* __restrict__ out)
{
    extern __shared__ float smem[];
    float* buf[2] = { smem, smem + PLANE_PAD };

    int t = threadIdx.x;

    // zero pads once
    if (t < 16) { buf[0][PLANE + t] = 0.0f; buf[1][PLANE + t] = 0.0f; }

    int p = blockIdx.x;
    if (p >= NPLANES) return;

    issue_plane_load(buf[0], input, p, t);

    int iter = 0;
    for (; p < NPLANES; p += NCTAS, ++iter) {
        int pn = p + NCTAS;
        if (pn < NPLANES) {
            issue_plane_load(buf[(iter + 1) & 1], input, pn, t);
            asm volatile("cp.async.wait_group 1;\n" ::: "memory");
        } else {
            asm volatile("cp.async.wait_group 0;\n" ::: "memory");
        }
        __syncthreads();
        compute_plane(buf[iter & 1], p, t, out);
        __syncthreads();   // all reads done before this buffer is refilled
    }
}

extern "C" void kernel_launch(void* const* d_in, const int* in_sizes, int n_in,
                              void* d_out, int out_size)
{
    const float* input = (const float*)d_in[0];
    const float* rois  = (const float*)d_in[1];
    float* out = (float*)d_out;

    cudaFuncSetAttribute(psroi_main,
                         cudaFuncAttributeMaxDynamicSharedMemorySize,
                         SMEM_BYTES);

    prep_kernel<<<1, 512>>>(rois);
    psroi_main<<<NCTAS, 256, SMEM_BYTES>>>(input, out);
}